// round 14
// baseline (speedup 1.0000x reference)
#include <cuda_runtime.h>
#include <cuda_fp16.h>
#include <cstdint>
#include <math.h>

#define NB 16384
#define NS 2048
#define ND 512
#define NM (NB + NS)   // 18432 rows: [x ; samples]

// ---------------------------------------------------------------------------
// Scratch (__device__ globals — allocation-free contract)
// ---------------------------------------------------------------------------
__device__ __align__(16) __half g_cath [NM * ND];            // [x ; samples] fp16
__device__ __align__(16) __half g_t1h  [NM * ND];            // dml hidden fp16
__device__ __align__(16) __half g_dmlh [NM * ND];            // [x_dml ; sam_new] fp16
__device__ __align__(16) __half g_W1h  [ND * ND];
__device__ __align__(16) __half g_W2h  [ND * ND];
__device__ __align__(16) __half g_Wn1h [NS * NS];
__device__ __align__(16) __half g_Wn2h [NS * NS];
__device__ __align__(16) float  g_Kf   [(long long)NB * NS]; // K fp32 (master)
__device__ __align__(16) __half g_Kh   [(long long)NB * NS]; // K fp16 (scaled)
__device__ __align__(16) __half g_Hh   [(long long)NB * NS]; // h fp16 (scaled)
__device__ __align__(16) float  g_nrm  [NM];
__device__ unsigned g_maxK;        // bit-pattern of max K (positive float)
__device__ unsigned g_done;        // RBF completion counter (self-resetting)
__device__ float    g_sc[4];       // {scK, invK, scH, invH} (powers of 2)

// ---------------------------------------------------------------------------
// Helpers
// ---------------------------------------------------------------------------
__device__ __forceinline__ uint32_t smem_u32(const void* p) {
    uint32_t a;
    asm("{ .reg .u64 t; cvta.to.shared.u64 t, %1; cvt.u32.u64 %0, t; }" : "=r"(a) : "l"(p));
    return a;
}
__device__ __forceinline__ float mish_f(float z) {
    float e  = __expf(z);
    float w  = 1.0f + e;
    float w2 = w * w;
    float r  = __fdividef(w2 - 1.0f, w2 + 1.0f);
    return (z > 30.0f) ? z : z * r;
}
__device__ __forceinline__ float rbf_f(float d2) {
    d2 = fmaxf(d2, 0.0f);
    float d;
    asm("sqrt.approx.f32 %0, %1;" : "=f"(d) : "f"(d2));
    return __expf(-d);
}
__device__ __forceinline__ void cp_async16(uint32_t saddr, const void* gaddr) {
    asm volatile("cp.async.cg.shared.global [%0], [%1], 16;" :: "r"(saddr), "l"(gaddr) : "memory");
}
__device__ __forceinline__ void cp_commit() {
    asm volatile("cp.async.commit_group;" ::: "memory");
}
__device__ __forceinline__ void ldsm4(uint32_t* d, uint32_t addr) {
    asm volatile("ldmatrix.sync.aligned.m8n8.x4.shared.b16 {%0,%1,%2,%3}, [%4];"
                 : "=r"(d[0]), "=r"(d[1]), "=r"(d[2]), "=r"(d[3]) : "r"(addr));
}
__device__ __forceinline__ void mma_f16(float* c, const uint32_t* a, uint32_t b0, uint32_t b1) {
    asm volatile("mma.sync.aligned.m16n8k16.row.col.f32.f16.f16.f32 "
                 "{%0,%1,%2,%3}, {%4,%5,%6,%7}, {%8,%9}, {%0,%1,%2,%3};"
                 : "+f"(c[0]), "+f"(c[1]), "+f"(c[2]), "+f"(c[3])
                 : "r"(a[0]), "r"(a[1]), "r"(a[2]), "r"(a[3]), "r"(b0), "r"(b1));
}

enum { EPI_NONE = 0, EPI_BIAS = 1, EPI_BIAS_MISH = 2, EPI_MISH = 3, EPI_RBF = 4 };

// ---------------------------------------------------------------------------
// fp16 mma.sync GEMM (measured-best shape: CTA 128x128, 8 warps 64x32, BK=64,
// 3-stage cp.async, 2 CTAs/SM — at ~97% of the legacy-HMMA rate; mainloop is
// final). TRACK_MAX: RBF also derives the K/H scales in its LAST CTA
// (atomic completion counter), eliminating the separate scales kernel.
// NORM_OUT: dml2 accumulates row norms of the STORED fp16 values.
// ---------------------------------------------------------------------------
#define A_BY     16384
#define STAGE_BY 32768
#define DSMEM_BY (3 * STAGE_BY)

template <int EPI, bool HALF_OUT, bool TRACK_MAX, bool NORM_OUT>
__global__ void __launch_bounds__(256, 2)
gemm_h(const __half* __restrict__ A, const __half* __restrict__ B,
       void* __restrict__ Cv, int M, int N, int K,
       const float* __restrict__ e1, const float* __restrict__ e2,
       const float* __restrict__ inv_in, const float* __restrict__ sc_out,
       float* __restrict__ nrm_out)
{
    extern __shared__ float smem[];
    const uint32_t sbase = smem_u32(smem);

    const int tid  = threadIdx.x;
    const int wid  = tid >> 5;
    const int lane = tid & 31;
    const int wm   = wid & 1;
    const int wn   = wid >> 1;
    const int nk   = K >> 6;         // BK = 64 halves

    const uint32_t rowA0 = blockIdx.y * 128;
    const uint32_t rowB0 = blockIdx.x * 128;

    uint32_t sOff[4], gAo[4], gBo[4];
#pragma unroll
    for (int i = 0; i < 4; i++) {
        int c = tid + i * 256, row = c >> 3, ch = c & 7;
        sOff[i] = (uint32_t)((row * 8 + (ch ^ (row & 7))) * 16);
        gAo[i]  = (rowA0 + row) * (uint32_t)K + ch * 8;
        gBo[i]  = (rowB0 + row) * (uint32_t)K + ch * 8;
    }

    auto issue = [&](int fi) {
        const int s = fi % 3;
        const uint32_t k0 = (uint32_t)fi * 64;
        const uint32_t sA = sbase + s * STAGE_BY;
        const uint32_t sB = sA + A_BY;
#pragma unroll
        for (int i = 0; i < 4; i++) cp_async16(sA + sOff[i], A + gAo[i] + k0);
#pragma unroll
        for (int i = 0; i < 4; i++) cp_async16(sB + sOff[i], B + gBo[i] + k0);
        cp_commit();
    };

    const int r8    = lane & 7;
    const int matId = lane >> 3;
    const int mrow  = ((matId & 1) << 3) + r8;
    const int mhi   = matId >> 1;
    uint32_t csw[4], aRow[4], bRow[2];
#pragma unroll
    for (int ks = 0; ks < 4; ks++) csw[ks] = (uint32_t)(((2 * ks + mhi) ^ r8) << 4);
#pragma unroll
    for (int t = 0; t < 4; t++) aRow[t] = (uint32_t)((wm * 64 + t * 16 + mrow) * 128);
#pragma unroll
    for (int t = 0; t < 2; t++) bRow[t] = (uint32_t)((wn * 32 + t * 16 + mrow) * 128) + A_BY;

    float acc[4][4][4];
#pragma unroll
    for (int mt = 0; mt < 4; mt++)
#pragma unroll
        for (int nt = 0; nt < 4; nt++)
#pragma unroll
            for (int q = 0; q < 4; q++) acc[mt][nt][q] = 0.0f;

    issue(0);
    issue(1);

#pragma unroll 1
    for (int fi = 0; fi < nk; ++fi) {
        if (fi + 1 < nk) asm volatile("cp.async.wait_group 1;" ::: "memory");
        else             asm volatile("cp.async.wait_group 0;" ::: "memory");
        __syncthreads();
        if (fi + 2 < nk) issue(fi + 2);

        const uint32_t st = sbase + (fi % 3) * STAGE_BY;
#pragma unroll
        for (int ks = 0; ks < 4; ks++) {
            uint32_t a[4][4], bb[2][4];
#pragma unroll
            for (int mt = 0; mt < 4; mt++) ldsm4(a[mt],  st + aRow[mt] + csw[ks]);
#pragma unroll
            for (int np = 0; np < 2; np++) ldsm4(bb[np], st + bRow[np] + csw[ks]);
#pragma unroll
            for (int mt = 0; mt < 4; mt++)
#pragma unroll
                for (int nt = 0; nt < 4; nt++)
                    mma_f16(acc[mt][nt], a[mt], bb[nt >> 1][nt & 1], bb[nt >> 1][2 + (nt & 1)]);
        }
    }

    // ---- epilogue ----
    const float invs = inv_in ? __ldg(inv_in) : 1.0f;
    const float osc  = sc_out ? __ldg(sc_out) : 1.0f;
    float lm = 0.0f;
    const int gid = lane >> 2, tig = lane & 3;
    float*  Cf = (float*)Cv;
    __half* Ch = (__half*)Cv;
#pragma unroll
    for (int mt = 0; mt < 4; mt++) {
        const int row = blockIdx.y * 128 + wm * 64 + mt * 16 + gid;
        float nr0 = 0.0f, nr8 = 0.0f;
        if (EPI == EPI_RBF) { nr0 = __ldg(e1 + row); nr8 = __ldg(e1 + row + 8); }
        float ns0 = 0.0f, ns8 = 0.0f;
#pragma unroll
        for (int nt = 0; nt < 4; nt++) {
            const int col = blockIdx.x * 128 + wn * 32 + nt * 8 + tig * 2;
            float ec0 = 0.0f, ec1 = 0.0f;
            if (EPI == EPI_BIAS || EPI == EPI_BIAS_MISH || EPI == EPI_RBF) {
                const float* ee = (EPI == EPI_RBF) ? e2 : e1;
                ec0 = __ldg(ee + col); ec1 = __ldg(ee + col + 1);
            }
            float v[4] = {acc[mt][nt][0], acc[mt][nt][1], acc[mt][nt][2], acc[mt][nt][3]};
#pragma unroll
            for (int q = 0; q < 4; q++) {
                float x = v[q] * invs;
                const float ec = (q & 1) ? ec1 : ec0;
                const float nr = (q < 2) ? nr0 : nr8;
                if (EPI == EPI_BIAS)           x = x + ec;
                else if (EPI == EPI_BIAS_MISH) x = mish_f(x + ec);
                else if (EPI == EPI_MISH)      x = mish_f(x);
                else if (EPI == EPI_RBF)       x = rbf_f(nr + ec - 2.0f * x);
                if (TRACK_MAX) lm = fmaxf(lm, fabsf(x));
                v[q] = x * osc;
            }
            if (HALF_OUT) {
                __half2 ha = __floats2half2_rn(v[0], v[1]);
                __half2 hb = __floats2half2_rn(v[2], v[3]);
                *(__half2*)(Ch + (size_t)row * N + col)       = ha;
                *(__half2*)(Ch + (size_t)(row + 8) * N + col) = hb;
                if (NORM_OUT) {
                    float2 fa = __half22float2(ha), fb = __half22float2(hb);
                    ns0 += fa.x * fa.x + fa.y * fa.y;
                    ns8 += fb.x * fb.x + fb.y * fb.y;
                }
            } else {
                // Kf master is read exactly once downstream: evict-first stores
                float2 o0 = make_float2(v[0], v[1]);
                float2 o1 = make_float2(v[2], v[3]);
                if (EPI == EPI_RBF) {
                    __stcs((float2*)(Cf + (size_t)row * N + col), o0);
                    __stcs((float2*)(Cf + (size_t)(row + 8) * N + col), o1);
                } else {
                    *(float2*)(Cf + (size_t)row * N + col)       = o0;
                    *(float2*)(Cf + (size_t)(row + 8) * N + col) = o1;
                }
            }
        }
        if (NORM_OUT) {
            ns0 += __shfl_down_sync(0xffffffffu, ns0, 2);
            ns0 += __shfl_down_sync(0xffffffffu, ns0, 1);
            ns8 += __shfl_down_sync(0xffffffffu, ns8, 2);
            ns8 += __shfl_down_sync(0xffffffffu, ns8, 1);
            if (tig == 0) {
                atomicAdd(nrm_out + row,     ns0);
                atomicAdd(nrm_out + row + 8, ns8);
            }
        }
    }
    if (TRACK_MAX) {
#pragma unroll
        for (int o = 16; o; o >>= 1) lm = fmaxf(lm, __shfl_xor_sync(0xffffffffu, lm, o));
        if (lane == 0) atomicMax(&g_maxK, __float_as_uint(lm));
        __syncthreads();
        // last CTA derives the scales (replaces a separate 1-thread kernel)
        if (tid == 0) {
            __threadfence();
            unsigned n = gridDim.x * gridDim.y;
            if (atomicAdd(&g_done, 1u) == n - 1u) {
                float m = __uint_as_float(*(volatile unsigned*)&g_maxK);
                int e = (m > 0.0f) ? ilogbf(m) : 0;
                g_sc[0] = exp2f((float)(13 - e));   // scK: maxK*scK in [2^13,2^14)
                g_sc[1] = exp2f((float)(e - 13));
                g_sc[2] = exp2f((float)(7 - e));    // scH: |h| < 64*maxK -> < 2^14
                g_sc[3] = exp2f((float)(e - 7));
                g_done = 0;                          // reset for next graph replay
                __threadfence();
            }
        }
    }
}

// ---------------------------------------------------------------------------
// Fused input conversion (grid-stride): all six fp32 inputs -> fp16;
// zero nrm and g_maxK.
// ---------------------------------------------------------------------------
__device__ __forceinline__ void cvt_gs(const float4* in, uint2* out, int n4) {
    for (int i = blockIdx.x * 256 + threadIdx.x; i < n4; i += gridDim.x * 256) {
        float4 v = in[i];
        __half2 a = __floats2half2_rn(v.x, v.y);
        __half2 b = __floats2half2_rn(v.z, v.w);
        uint2 o;
        o.x = *(const unsigned*)&a;
        o.y = *(const unsigned*)&b;
        out[i] = o;
    }
}

__global__ void __launch_bounds__(256)
f2h_all(const float4* x, const float4* sm, const float4* w1, const float4* w2,
        const float4* wn1, const float4* wn2,
        uint2* cath, uint2* w1h, uint2* w2h, uint2* wn1h, uint2* wn2h,
        float4* nrm)
{
    switch (blockIdx.y) {
        case 0: cvt_gs(x,   cath,               NB * ND / 4); break;
        case 1: cvt_gs(sm,  cath + NB * ND / 4, NS * ND / 4); break;
        case 2: cvt_gs(w1,  w1h,                ND * ND / 4);
                for (int j = blockIdx.x * 256 + threadIdx.x; j < NM / 4; j += gridDim.x * 256)
                    nrm[j] = make_float4(0.f, 0.f, 0.f, 0.f);
                if (blockIdx.x == 0 && threadIdx.x == 0) g_maxK = 0u;
                break;
        case 3: cvt_gs(w2,  w2h,                ND * ND / 4); break;
        case 4: cvt_gs(wn1, wn1h,               NS * NS / 4); break;
        case 5: cvt_gs(wn2, wn2h,               NS * NS / 4); break;
    }
}

// ---------------------------------------------------------------------------
// K master -> scaled fp16. Grid-stride, 4 x float4 per iter, evict-first
// loads (Kf is dead after this).
// ---------------------------------------------------------------------------
__global__ void __launch_bounds__(256)
f2h_scaled(const float4* __restrict__ in, uint2* __restrict__ out, int n4,
           const float* __restrict__ scale)
{
    const float s = __ldg(scale);
    const int stride = gridDim.x * 256;
    for (int i0 = blockIdx.x * 256 + threadIdx.x; i0 < n4; i0 += stride * 4) {
#pragma unroll
        for (int t = 0; t < 4; t++) {
            int i = i0 + t * stride;
            if (i < n4) {
                float4 v = __ldcs(in + i);
                __half2 a = __floats2half2_rn(v.x * s, v.y * s);
                __half2 b = __floats2half2_rn(v.z * s, v.w * s);
                uint2 o;
                o.x = *(const unsigned*)&a;
                o.y = *(const unsigned*)&b;
                out[i] = o;
            }
        }
    }
}

// ---------------------------------------------------------------------------
// Launch — 7 launches; our index 3 = RBF GEMM (grid 2048) = ncu capture slot.
// ---------------------------------------------------------------------------
extern "C" void kernel_launch(void* const* d_in, const int* in_sizes, int n_in,
                              void* d_out, int out_size)
{
    const float* x   = (const float*)d_in[0];
    const float* sm  = (const float*)d_in[1];
    const float* W1  = (const float*)d_in[2];
    const float* b1  = (const float*)d_in[3];
    const float* W2  = (const float*)d_in[4];
    const float* b2  = (const float*)d_in[5];
    const float* Wn1 = (const float*)d_in[6];
    const float* Wn2 = (const float*)d_in[7];
    float* out = (float*)d_out;

    __half *cath, *t1h, *dmlh, *W1h, *W2h, *Wn1h, *Wn2h, *Kh, *Hh;
    float *Kf, *nrm, *sc;
    cudaGetSymbolAddress((void**)&cath, g_cath);
    cudaGetSymbolAddress((void**)&t1h,  g_t1h);
    cudaGetSymbolAddress((void**)&dmlh, g_dmlh);
    cudaGetSymbolAddress((void**)&W1h,  g_W1h);
    cudaGetSymbolAddress((void**)&W2h,  g_W2h);
    cudaGetSymbolAddress((void**)&Wn1h, g_Wn1h);
    cudaGetSymbolAddress((void**)&Wn2h, g_Wn2h);
    cudaGetSymbolAddress((void**)&Kf,   g_Kf);
    cudaGetSymbolAddress((void**)&Kh,   g_Kh);
    cudaGetSymbolAddress((void**)&Hh,   g_Hh);
    cudaGetSymbolAddress((void**)&nrm,  g_nrm);
    cudaGetSymbolAddress((void**)&sc,   g_sc);

    #define SETSM(KER) cudaFuncSetAttribute(KER, cudaFuncAttributeMaxDynamicSharedMemorySize, DSMEM_BY)
    SETSM((gemm_h<EPI_BIAS_MISH, true,  false, false>));
    SETSM((gemm_h<EPI_BIAS,      true,  false, true >));
    SETSM((gemm_h<EPI_RBF,       false, true,  false>));
    SETSM((gemm_h<EPI_MISH,      true,  false, false>));
    SETSM((gemm_h<EPI_NONE,      false, false, false>));
    #undef SETSM

    const dim3 blk(256);
    const dim3 gDml(ND / 128, NM / 128);
    const dim3 gBig(NS / 128, NB / 128);

    // idx 0: fused conversion of ALL inputs + zero nrm/maxK
    f2h_all<<<dim3(1024, 6), 256>>>(
        (const float4*)x, (const float4*)sm, (const float4*)W1, (const float4*)W2,
        (const float4*)Wn1, (const float4*)Wn2,
        (uint2*)cath, (uint2*)W1h, (uint2*)W2h, (uint2*)Wn1h, (uint2*)Wn2h,
        (float4*)nrm);

    // idx 1: dml layer 1 (fused x+samples)
    gemm_h<EPI_BIAS_MISH, true, false, false><<<gDml, blk, DSMEM_BY>>>(
        cath, W1h, t1h, NM, ND, ND, b1, nullptr, nullptr, nullptr, nullptr);

    // idx 2: dml layer 2 + fused row norms (of stored fp16 values)
    gemm_h<EPI_BIAS, true, false, true><<<gDml, blk, DSMEM_BY>>>(
        t1h, W2h, dmlh, NM, ND, ND, b2, nullptr, nullptr, nullptr, nrm);

    // idx 3: RBF GEMM — ncu capture target; last CTA derives scales
    gemm_h<EPI_RBF, false, true, false><<<gBig, blk, DSMEM_BY>>>(
        dmlh, dmlh + (size_t)NB * ND, Kf, NB, NS, ND, nrm, nrm + NB,
        nullptr, nullptr, nullptr);

    // idx 4: K -> scaled fp16 (grid-stride, evict-first reads)
    f2h_scaled<<<2048, 256>>>(
        (const float4*)Kf, (uint2*)Kh, (int)((long long)NB * NS / 4), sc);

    // idx 5: h' = mish((K' @ Wn1^T)*invK) * scH -> fp16 direct
    gemm_h<EPI_MISH, true, false, false><<<gBig, blk, DSMEM_BY>>>(
        Kh, Wn1h, Hh, NB, NS, NS, nullptr, nullptr, sc + 1, sc + 2, nullptr);

    // idx 6: out = (h' @ Wn2^T) * invH  (fp32)
    gemm_h<EPI_NONE, false, false, false><<<gBig, blk, DSMEM_BY>>>(
        Hh, Wn2h, out, NB, NS, NS, nullptr, nullptr, sc + 3, nullptr, nullptr);
}

// round 15
// speedup vs baseline: 1.0086x; 1.0086x over previous
#include <cuda_runtime.h>
#include <cuda_fp16.h>
#include <cstdint>
#include <math.h>

#define NB 16384
#define NS 2048
#define ND 512
#define NM (NB + NS)   // 18432 rows: [x ; samples]

// ---------------------------------------------------------------------------
// Scratch (__device__ globals — allocation-free contract)
// ---------------------------------------------------------------------------
__device__ __align__(16) __half g_cath [NM * ND];            // [x ; samples] fp16
__device__ __align__(16) __half g_t1h  [NM * ND];            // dml hidden fp16
__device__ __align__(16) __half g_dmlh [NM * ND];            // [x_dml ; sam_new] fp16
__device__ __align__(16) __half g_W1h  [ND * ND];
__device__ __align__(16) __half g_W2h  [ND * ND];
__device__ __align__(16) __half g_Wn1h [NS * NS];
__device__ __align__(16) __half g_Wn2h [NS * NS];
__device__ __align__(16) float  g_Kf   [(long long)NB * NS]; // d2 fp32 (master)
__device__ __align__(16) __half g_Kh   [(long long)NB * NS]; // K fp16 (scaled)
__device__ __align__(16) __half g_Hh   [(long long)NB * NS]; // h fp16 (scaled)
__device__ __align__(16) float  g_nrm  [NM];
__device__ unsigned g_minD2;       // bit-pattern of min d2 (nonneg float)
__device__ unsigned g_done;        // RBF completion counter (self-resetting)
__device__ float    g_sc[4];       // {s13 (exponent addend), invK, scH, invH}

// ---------------------------------------------------------------------------
// Helpers
// ---------------------------------------------------------------------------
__device__ __forceinline__ uint32_t smem_u32(const void* p) {
    uint32_t a;
    asm("{ .reg .u64 t; cvta.to.shared.u64 t, %1; cvt.u32.u64 %0, t; }" : "=r"(a) : "l"(p));
    return a;
}
__device__ __forceinline__ float mish_f(float z) {
    float e  = __expf(z);
    float w  = 1.0f + e;
    float w2 = w * w;
    float r  = __fdividef(w2 - 1.0f, w2 + 1.0f);
    return (z > 30.0f) ? z : z * r;
}
__device__ __forceinline__ void cp_async16(uint32_t saddr, const void* gaddr) {
    asm volatile("cp.async.cg.shared.global [%0], [%1], 16;" :: "r"(saddr), "l"(gaddr) : "memory");
}
__device__ __forceinline__ void cp_commit() {
    asm volatile("cp.async.commit_group;" ::: "memory");
}
__device__ __forceinline__ void ldsm4(uint32_t* d, uint32_t addr) {
    asm volatile("ldmatrix.sync.aligned.m8n8.x4.shared.b16 {%0,%1,%2,%3}, [%4];"
                 : "=r"(d[0]), "=r"(d[1]), "=r"(d[2]), "=r"(d[3]) : "r"(addr));
}
__device__ __forceinline__ void mma_f16(float* c, const uint32_t* a, uint32_t b0, uint32_t b1) {
    asm volatile("mma.sync.aligned.m16n8k16.row.col.f32.f16.f16.f32 "
                 "{%0,%1,%2,%3}, {%4,%5,%6,%7}, {%8,%9}, {%0,%1,%2,%3};"
                 : "+f"(c[0]), "+f"(c[1]), "+f"(c[2]), "+f"(c[3])
                 : "r"(a[0]), "r"(a[1]), "r"(a[2]), "r"(a[3]), "r"(b0), "r"(b1));
}

enum { EPI_NONE = 0, EPI_BIAS = 1, EPI_BIAS_MISH = 2, EPI_MISH = 3, EPI_D2 = 4 };

// ---------------------------------------------------------------------------
// fp16 mma.sync GEMM (measured-best shape: CTA 128x128, 8 warps 64x32, BK=64,
// 3-stage cp.async, 2 CTAs/SM). EPI_D2 writes RAW squared distances (no MUFU
// on the GEMM's critical path — exp/sqrt moved to the memory-bound convert
// pass) and tracks min d2; the LAST CTA derives the K/H scales from it.
// NORM_OUT: dml2 accumulates row norms of the STORED fp16 values.
// ---------------------------------------------------------------------------
#define A_BY     16384
#define STAGE_BY 32768
#define DSMEM_BY (3 * STAGE_BY)

template <int EPI, bool HALF_OUT, bool TRACK_MIN, bool NORM_OUT>
__global__ void __launch_bounds__(256, 2)
gemm_h(const __half* __restrict__ A, const __half* __restrict__ B,
       void* __restrict__ Cv, int M, int N, int K,
       const float* __restrict__ e1, const float* __restrict__ e2,
       const float* __restrict__ inv_in, const float* __restrict__ sc_out,
       float* __restrict__ nrm_out)
{
    extern __shared__ float smem[];
    const uint32_t sbase = smem_u32(smem);

    const int tid  = threadIdx.x;
    const int wid  = tid >> 5;
    const int lane = tid & 31;
    const int wm   = wid & 1;
    const int wn   = wid >> 1;
    const int nk   = K >> 6;         // BK = 64 halves

    const uint32_t rowA0 = blockIdx.y * 128;
    const uint32_t rowB0 = blockIdx.x * 128;

    uint32_t sOff[4], gAo[4], gBo[4];
#pragma unroll
    for (int i = 0; i < 4; i++) {
        int c = tid + i * 256, row = c >> 3, ch = c & 7;
        sOff[i] = (uint32_t)((row * 8 + (ch ^ (row & 7))) * 16);
        gAo[i]  = (rowA0 + row) * (uint32_t)K + ch * 8;
        gBo[i]  = (rowB0 + row) * (uint32_t)K + ch * 8;
    }

    auto issue = [&](int fi) {
        const int s = fi % 3;
        const uint32_t k0 = (uint32_t)fi * 64;
        const uint32_t sA = sbase + s * STAGE_BY;
        const uint32_t sB = sA + A_BY;
#pragma unroll
        for (int i = 0; i < 4; i++) cp_async16(sA + sOff[i], A + gAo[i] + k0);
#pragma unroll
        for (int i = 0; i < 4; i++) cp_async16(sB + sOff[i], B + gBo[i] + k0);
        cp_commit();
    };

    const int r8    = lane & 7;
    const int matId = lane >> 3;
    const int mrow  = ((matId & 1) << 3) + r8;
    const int mhi   = matId >> 1;
    uint32_t csw[4], aRow[4], bRow[2];
#pragma unroll
    for (int ks = 0; ks < 4; ks++) csw[ks] = (uint32_t)(((2 * ks + mhi) ^ r8) << 4);
#pragma unroll
    for (int t = 0; t < 4; t++) aRow[t] = (uint32_t)((wm * 64 + t * 16 + mrow) * 128);
#pragma unroll
    for (int t = 0; t < 2; t++) bRow[t] = (uint32_t)((wn * 32 + t * 16 + mrow) * 128) + A_BY;

    float acc[4][4][4];
#pragma unroll
    for (int mt = 0; mt < 4; mt++)
#pragma unroll
        for (int nt = 0; nt < 4; nt++)
#pragma unroll
            for (int q = 0; q < 4; q++) acc[mt][nt][q] = 0.0f;

    issue(0);
    issue(1);

#pragma unroll 1
    for (int fi = 0; fi < nk; ++fi) {
        if (fi + 1 < nk) asm volatile("cp.async.wait_group 1;" ::: "memory");
        else             asm volatile("cp.async.wait_group 0;" ::: "memory");
        __syncthreads();
        if (fi + 2 < nk) issue(fi + 2);

        const uint32_t st = sbase + (fi % 3) * STAGE_BY;
#pragma unroll
        for (int ks = 0; ks < 4; ks++) {
            uint32_t a[4][4], bb[2][4];
#pragma unroll
            for (int mt = 0; mt < 4; mt++) ldsm4(a[mt],  st + aRow[mt] + csw[ks]);
#pragma unroll
            for (int np = 0; np < 2; np++) ldsm4(bb[np], st + bRow[np] + csw[ks]);
#pragma unroll
            for (int mt = 0; mt < 4; mt++)
#pragma unroll
                for (int nt = 0; nt < 4; nt++)
                    mma_f16(acc[mt][nt], a[mt], bb[nt >> 1][nt & 1], bb[nt >> 1][2 + (nt & 1)]);
        }
    }

    // ---- epilogue ----
    const float invs = inv_in ? __ldg(inv_in) : 1.0f;
    const float osc  = sc_out ? __ldg(sc_out) : 1.0f;
    float lmin = 3.4e38f;
    const int gid = lane >> 2, tig = lane & 3;
    float*  Cf = (float*)Cv;
    __half* Ch = (__half*)Cv;
#pragma unroll
    for (int mt = 0; mt < 4; mt++) {
        const int row = blockIdx.y * 128 + wm * 64 + mt * 16 + gid;
        float nr0 = 0.0f, nr8 = 0.0f;
        if (EPI == EPI_D2) { nr0 = __ldg(e1 + row); nr8 = __ldg(e1 + row + 8); }
        float ns0 = 0.0f, ns8 = 0.0f;
#pragma unroll
        for (int nt = 0; nt < 4; nt++) {
            const int col = blockIdx.x * 128 + wn * 32 + nt * 8 + tig * 2;
            float ec0 = 0.0f, ec1 = 0.0f;
            if (EPI == EPI_BIAS || EPI == EPI_BIAS_MISH || EPI == EPI_D2) {
                const float* ee = (EPI == EPI_D2) ? e2 : e1;
                ec0 = __ldg(ee + col); ec1 = __ldg(ee + col + 1);
            }
            float v[4] = {acc[mt][nt][0], acc[mt][nt][1], acc[mt][nt][2], acc[mt][nt][3]};
#pragma unroll
            for (int q = 0; q < 4; q++) {
                float x = v[q] * invs;
                const float ec = (q & 1) ? ec1 : ec0;
                const float nr = (q < 2) ? nr0 : nr8;
                if (EPI == EPI_BIAS)           x = x + ec;
                else if (EPI == EPI_BIAS_MISH) x = mish_f(x + ec);
                else if (EPI == EPI_MISH)      x = mish_f(x);
                else if (EPI == EPI_D2) {      // raw clamped d2 — NO MUFU here
                    x = fmaxf(nr + ec - 2.0f * x, 0.0f);
                    if (TRACK_MIN) lmin = fminf(lmin, x);
                }
                v[q] = x * osc;
            }
            if (HALF_OUT) {
                __half2 ha = __floats2half2_rn(v[0], v[1]);
                __half2 hb = __floats2half2_rn(v[2], v[3]);
                *(__half2*)(Ch + (size_t)row * N + col)       = ha;
                *(__half2*)(Ch + (size_t)(row + 8) * N + col) = hb;
                if (NORM_OUT) {
                    float2 fa = __half22float2(ha), fb = __half22float2(hb);
                    ns0 += fa.x * fa.x + fa.y * fa.y;
                    ns8 += fb.x * fb.x + fb.y * fb.y;
                }
            } else {
                float2 o0 = make_float2(v[0], v[1]);
                float2 o1 = make_float2(v[2], v[3]);
                if (EPI == EPI_D2) {   // master read exactly once: evict-first
                    __stcs((float2*)(Cf + (size_t)row * N + col), o0);
                    __stcs((float2*)(Cf + (size_t)(row + 8) * N + col), o1);
                } else {
                    *(float2*)(Cf + (size_t)row * N + col)       = o0;
                    *(float2*)(Cf + (size_t)(row + 8) * N + col) = o1;
                }
            }
        }
        if (NORM_OUT) {
            ns0 += __shfl_down_sync(0xffffffffu, ns0, 2);
            ns0 += __shfl_down_sync(0xffffffffu, ns0, 1);
            ns8 += __shfl_down_sync(0xffffffffu, ns8, 2);
            ns8 += __shfl_down_sync(0xffffffffu, ns8, 1);
            if (tig == 0) {
                atomicAdd(nrm_out + row,     ns0);
                atomicAdd(nrm_out + row + 8, ns8);
            }
        }
    }
    if (TRACK_MIN) {
#pragma unroll
        for (int o = 16; o; o >>= 1) lmin = fminf(lmin, __shfl_xor_sync(0xffffffffu, lmin, o));
        if (lane == 0) atomicMin(&g_minD2, __float_as_uint(lmin));  // d2 >= 0: uint order ok
        __syncthreads();
        // last CTA derives the scales (no separate kernel)
        if (tid == 0) {
            __threadfence();
            unsigned n = gridDim.x * gridDim.y;
            if (atomicAdd(&g_done, 1u) == n - 1u) {
                float dmin = sqrtf(__uint_as_float(*(volatile unsigned*)&g_minD2));
                // E ~= ilogb(maxK), maxK = exp(-dmin); +/-1 slack keeps
                // maxK*scK within [2^12, 2^15] — far below fp16 max.
                int E = (int)floorf(-dmin * 1.44269504f);
                g_sc[0] = (float)(13 - E);            // exponent addend for exp2
                g_sc[1] = exp2f((float)(E - 13));     // invK
                g_sc[2] = exp2f((float)(7 - E));      // scH  (|h| < 64*maxK)
                g_sc[3] = exp2f((float)(E - 7));      // invH
                g_done = 0;                           // reset for next replay
                __threadfence();
            }
        }
    }
}

// ---------------------------------------------------------------------------
// Fused input conversion (grid-stride): all six fp32 inputs -> fp16;
// zero nrm; init g_minD2 = +inf.
// ---------------------------------------------------------------------------
__device__ __forceinline__ void cvt_gs(const float4* in, uint2* out, int n4) {
    for (int i = blockIdx.x * 256 + threadIdx.x; i < n4; i += gridDim.x * 256) {
        float4 v = in[i];
        __half2 a = __floats2half2_rn(v.x, v.y);
        __half2 b = __floats2half2_rn(v.z, v.w);
        uint2 o;
        o.x = *(const unsigned*)&a;
        o.y = *(const unsigned*)&b;
        out[i] = o;
    }
}

__global__ void __launch_bounds__(256)
f2h_all(const float4* x, const float4* sm, const float4* w1, const float4* w2,
        const float4* wn1, const float4* wn2,
        uint2* cath, uint2* w1h, uint2* w2h, uint2* wn1h, uint2* wn2h,
        float4* nrm)
{
    switch (blockIdx.y) {
        case 0: cvt_gs(x,   cath,               NB * ND / 4); break;
        case 1: cvt_gs(sm,  cath + NB * ND / 4, NS * ND / 4); break;
        case 2: cvt_gs(w1,  w1h,                ND * ND / 4);
                for (int j = blockIdx.x * 256 + threadIdx.x; j < NM / 4; j += gridDim.x * 256)
                    nrm[j] = make_float4(0.f, 0.f, 0.f, 0.f);
                if (blockIdx.x == 0 && threadIdx.x == 0) g_minD2 = 0x7F800000u; // +inf
                break;
        case 3: cvt_gs(w2,  w2h,                ND * ND / 4); break;
        case 4: cvt_gs(wn1, wn1h,               NS * NS / 4); break;
        case 5: cvt_gs(wn2, wn2h,               NS * NS / 4); break;
    }
}

// ---------------------------------------------------------------------------
// d2 master -> scaled fp16 K: K*2^s = exp2(s - sqrt(d2)*log2e).
// Memory-bound; the MUFU work (sqrt + ex2) hides under DRAM latency.
// ---------------------------------------------------------------------------
__device__ __forceinline__ float d2K(float d2, float s13) {
    float d;
    asm("sqrt.approx.f32 %0, %1;" : "=f"(d) : "f"(d2));
    return exp2f(fmaf(-d, 1.44269504f, s13));
}

__global__ void __launch_bounds__(256)
d2_to_Kh(const float4* __restrict__ in, uint2* __restrict__ out, int n4,
         const float* __restrict__ sc)
{
    const float s13 = __ldg(sc);
    const int stride = gridDim.x * 256;
    for (int i0 = blockIdx.x * 256 + threadIdx.x; i0 < n4; i0 += stride * 4) {
#pragma unroll
        for (int t = 0; t < 4; t++) {
            int i = i0 + t * stride;
            if (i < n4) {
                float4 v = __ldcs(in + i);
                __half2 a = __floats2half2_rn(d2K(v.x, s13), d2K(v.y, s13));
                __half2 b = __floats2half2_rn(d2K(v.z, s13), d2K(v.w, s13));
                uint2 o;
                o.x = *(const unsigned*)&a;
                o.y = *(const unsigned*)&b;
                out[i] = o;
            }
        }
    }
}

// ---------------------------------------------------------------------------
// Launch — 7 launches; our index 3 = d2 GEMM (grid 2048) = ncu capture slot.
// ---------------------------------------------------------------------------
extern "C" void kernel_launch(void* const* d_in, const int* in_sizes, int n_in,
                              void* d_out, int out_size)
{
    const float* x   = (const float*)d_in[0];
    const float* sm  = (const float*)d_in[1];
    const float* W1  = (const float*)d_in[2];
    const float* b1  = (const float*)d_in[3];
    const float* W2  = (const float*)d_in[4];
    const float* b2  = (const float*)d_in[5];
    const float* Wn1 = (const float*)d_in[6];
    const float* Wn2 = (const float*)d_in[7];
    float* out = (float*)d_out;

    __half *cath, *t1h, *dmlh, *W1h, *W2h, *Wn1h, *Wn2h, *Kh, *Hh;
    float *Kf, *nrm, *sc;
    cudaGetSymbolAddress((void**)&cath, g_cath);
    cudaGetSymbolAddress((void**)&t1h,  g_t1h);
    cudaGetSymbolAddress((void**)&dmlh, g_dmlh);
    cudaGetSymbolAddress((void**)&W1h,  g_W1h);
    cudaGetSymbolAddress((void**)&W2h,  g_W2h);
    cudaGetSymbolAddress((void**)&Wn1h, g_Wn1h);
    cudaGetSymbolAddress((void**)&Wn2h, g_Wn2h);
    cudaGetSymbolAddress((void**)&Kf,   g_Kf);
    cudaGetSymbolAddress((void**)&Kh,   g_Kh);
    cudaGetSymbolAddress((void**)&Hh,   g_Hh);
    cudaGetSymbolAddress((void**)&nrm,  g_nrm);
    cudaGetSymbolAddress((void**)&sc,   g_sc);

    #define SETSM(KER) cudaFuncSetAttribute(KER, cudaFuncAttributeMaxDynamicSharedMemorySize, DSMEM_BY)
    SETSM((gemm_h<EPI_BIAS_MISH, true,  false, false>));
    SETSM((gemm_h<EPI_BIAS,      true,  false, true >));
    SETSM((gemm_h<EPI_D2,        false, true,  false>));
    SETSM((gemm_h<EPI_MISH,      true,  false, false>));
    SETSM((gemm_h<EPI_NONE,      false, false, false>));
    #undef SETSM

    const dim3 blk(256);
    const dim3 gDml(ND / 128, NM / 128);
    const dim3 gBig(NS / 128, NB / 128);

    // idx 0: fused conversion of ALL inputs + zero nrm / init minD2
    f2h_all<<<dim3(1024, 6), 256>>>(
        (const float4*)x, (const float4*)sm, (const float4*)W1, (const float4*)W2,
        (const float4*)Wn1, (const float4*)Wn2,
        (uint2*)cath, (uint2*)W1h, (uint2*)W2h, (uint2*)Wn1h, (uint2*)Wn2h,
        (float4*)nrm);

    // idx 1: dml layer 1 (fused x+samples)
    gemm_h<EPI_BIAS_MISH, true, false, false><<<gDml, blk, DSMEM_BY>>>(
        cath, W1h, t1h, NM, ND, ND, b1, nullptr, nullptr, nullptr, nullptr);

    // idx 2: dml layer 2 + fused row norms (of stored fp16 values)
    gemm_h<EPI_BIAS, true, false, true><<<gDml, blk, DSMEM_BY>>>(
        t1h, W2h, dmlh, NM, ND, ND, b2, nullptr, nullptr, nullptr, nrm);

    // idx 3: d2 GEMM — ncu capture target; MUFU-free epilogue; last CTA
    // derives the K/H scales from min d2
    gemm_h<EPI_D2, false, true, false><<<gBig, blk, DSMEM_BY>>>(
        dmlh, dmlh + (size_t)NB * ND, Kf, NB, NS, ND, nrm, nrm + NB,
        nullptr, nullptr, nullptr);

    // idx 4: d2 -> scaled fp16 K (exp/sqrt here, hidden under DRAM)
    d2_to_Kh<<<2048, 256>>>(
        (const float4*)Kf, (uint2*)Kh, (int)((long long)NB * NS / 4), sc);

    // idx 5: h' = mish((K' @ Wn1^T)*invK) * scH -> fp16 direct
    gemm_h<EPI_MISH, true, false, false><<<gBig, blk, DSMEM_BY>>>(
        Kh, Wn1h, Hh, NB, NS, NS, nullptr, nullptr, sc + 1, sc + 2, nullptr);

    // idx 6: out = (h' @ Wn2^T) * invH  (fp32)
    gemm_h<EPI_NONE, false, false, false><<<gBig, blk, DSMEM_BY>>>(
        Hh, Wn2h, out, NB, NS, NS, nullptr, nullptr, sc + 3, nullptr, nullptr);
}

// round 16
// speedup vs baseline: 1.0124x; 1.0038x over previous
#include <cuda_runtime.h>
#include <cuda_fp16.h>
#include <cstdint>
#include <math.h>

#define NB 16384
#define NS 2048
#define ND 512
#define NM (NB + NS)   // 18432 rows: [x ; samples]

// ---------------------------------------------------------------------------
// Scratch (__device__ globals — allocation-free contract)
// ---------------------------------------------------------------------------
__device__ __align__(16) __half g_cath [NM * ND];            // [x ; samples] fp16
__device__ __align__(16) __half g_t1h  [NM * ND];            // dml hidden fp16
__device__ __align__(16) __half g_dmlh [NM * ND];            // [x_dml ; sam_new] fp16
__device__ __align__(16) __half g_W1h  [ND * ND];
__device__ __align__(16) __half g_W2h  [ND * ND];
__device__ __align__(16) __half g_Wn1h [NS * NS];
__device__ __align__(16) __half g_Wn2h [NS * NS];
__device__ __align__(16) float  g_Kf   [(long long)NB * NS]; // d2 fp32 (master)
__device__ __align__(16) __half g_Kh   [(long long)NB * NS]; // K fp16 (scaled)
__device__ __align__(16) __half g_Hh   [(long long)NB * NS]; // h fp16 (scaled)
__device__ __align__(16) float  g_nrm  [NM];
__device__ unsigned g_minD2;       // bit-pattern of min d2 (nonneg float)
__device__ unsigned g_done;        // RBF completion counter (self-resetting)
__device__ float    g_sc[4];       // {s13 (exponent addend), invK, scH, invH}

// ---------------------------------------------------------------------------
// Helpers
// ---------------------------------------------------------------------------
__device__ __forceinline__ uint32_t smem_u32(const void* p) {
    uint32_t a;
    asm("{ .reg .u64 t; cvta.to.shared.u64 t, %1; cvt.u32.u64 %0, t; }" : "=r"(a) : "l"(p));
    return a;
}
__device__ __forceinline__ float mish_f(float z) {
    float e  = __expf(z);
    float w  = 1.0f + e;
    float w2 = w * w;
    float r  = __fdividef(w2 - 1.0f, w2 + 1.0f);
    return (z > 30.0f) ? z : z * r;
}
__device__ __forceinline__ void cp_async16(uint32_t saddr, const void* gaddr) {
    asm volatile("cp.async.cg.shared.global [%0], [%1], 16;" :: "r"(saddr), "l"(gaddr) : "memory");
}
__device__ __forceinline__ void cp_commit() {
    asm volatile("cp.async.commit_group;" ::: "memory");
}
__device__ __forceinline__ void ldsm4(uint32_t* d, uint32_t addr) {
    asm volatile("ldmatrix.sync.aligned.m8n8.x4.shared.b16 {%0,%1,%2,%3}, [%4];"
                 : "=r"(d[0]), "=r"(d[1]), "=r"(d[2]), "=r"(d[3]) : "r"(addr));
}
__device__ __forceinline__ void mma_f16(float* c, const uint32_t* a, uint32_t b0, uint32_t b1) {
    asm volatile("mma.sync.aligned.m16n8k16.row.col.f32.f16.f16.f32 "
                 "{%0,%1,%2,%3}, {%4,%5,%6,%7}, {%8,%9}, {%0,%1,%2,%3};"
                 : "+f"(c[0]), "+f"(c[1]), "+f"(c[2]), "+f"(c[3])
                 : "r"(a[0]), "r"(a[1]), "r"(a[2]), "r"(a[3]), "r"(b0), "r"(b1));
}

enum { EPI_NONE = 0, EPI_BIAS = 1, EPI_BIAS_MISH = 2, EPI_MISH = 3, EPI_D2 = 4 };

// ---------------------------------------------------------------------------
// fp16 mma.sync GEMM (measured-best shape: CTA 128x128, 8 warps 64x32, BK=64,
// 3-stage cp.async, 2 CTAs/SM). EPI_D2 writes RAW squared distances with
// NORMAL store policy — the 128MB master nearly fits the ~126MB L2, so the
// immediately-following convert pass reads mostly from L2 (the R14 __stcs
// evict-first store was backwards and is removed). Last CTA derives scales.
// NORM_OUT: dml2 accumulates row norms of the STORED fp16 values.
// ---------------------------------------------------------------------------
#define A_BY     16384
#define STAGE_BY 32768
#define DSMEM_BY (3 * STAGE_BY)

template <int EPI, bool HALF_OUT, bool TRACK_MIN, bool NORM_OUT>
__global__ void __launch_bounds__(256, 2)
gemm_h(const __half* __restrict__ A, const __half* __restrict__ B,
       void* __restrict__ Cv, int M, int N, int K,
       const float* __restrict__ e1, const float* __restrict__ e2,
       const float* __restrict__ inv_in, const float* __restrict__ sc_out,
       float* __restrict__ nrm_out)
{
    extern __shared__ float smem[];
    const uint32_t sbase = smem_u32(smem);

    const int tid  = threadIdx.x;
    const int wid  = tid >> 5;
    const int lane = tid & 31;
    const int wm   = wid & 1;
    const int wn   = wid >> 1;
    const int nk   = K >> 6;         // BK = 64 halves

    const uint32_t rowA0 = blockIdx.y * 128;
    const uint32_t rowB0 = blockIdx.x * 128;

    uint32_t sOff[4], gAo[4], gBo[4];
#pragma unroll
    for (int i = 0; i < 4; i++) {
        int c = tid + i * 256, row = c >> 3, ch = c & 7;
        sOff[i] = (uint32_t)((row * 8 + (ch ^ (row & 7))) * 16);
        gAo[i]  = (rowA0 + row) * (uint32_t)K + ch * 8;
        gBo[i]  = (rowB0 + row) * (uint32_t)K + ch * 8;
    }

    auto issue = [&](int fi) {
        const int s = fi % 3;
        const uint32_t k0 = (uint32_t)fi * 64;
        const uint32_t sA = sbase + s * STAGE_BY;
        const uint32_t sB = sA + A_BY;
#pragma unroll
        for (int i = 0; i < 4; i++) cp_async16(sA + sOff[i], A + gAo[i] + k0);
#pragma unroll
        for (int i = 0; i < 4; i++) cp_async16(sB + sOff[i], B + gBo[i] + k0);
        cp_commit();
    };

    const int r8    = lane & 7;
    const int matId = lane >> 3;
    const int mrow  = ((matId & 1) << 3) + r8;
    const int mhi   = matId >> 1;
    uint32_t csw[4], aRow[4], bRow[2];
#pragma unroll
    for (int ks = 0; ks < 4; ks++) csw[ks] = (uint32_t)(((2 * ks + mhi) ^ r8) << 4);
#pragma unroll
    for (int t = 0; t < 4; t++) aRow[t] = (uint32_t)((wm * 64 + t * 16 + mrow) * 128);
#pragma unroll
    for (int t = 0; t < 2; t++) bRow[t] = (uint32_t)((wn * 32 + t * 16 + mrow) * 128) + A_BY;

    float acc[4][4][4];
#pragma unroll
    for (int mt = 0; mt < 4; mt++)
#pragma unroll
        for (int nt = 0; nt < 4; nt++)
#pragma unroll
            for (int q = 0; q < 4; q++) acc[mt][nt][q] = 0.0f;

    issue(0);
    issue(1);

#pragma unroll 1
    for (int fi = 0; fi < nk; ++fi) {
        if (fi + 1 < nk) asm volatile("cp.async.wait_group 1;" ::: "memory");
        else             asm volatile("cp.async.wait_group 0;" ::: "memory");
        __syncthreads();
        if (fi + 2 < nk) issue(fi + 2);

        const uint32_t st = sbase + (fi % 3) * STAGE_BY;
#pragma unroll
        for (int ks = 0; ks < 4; ks++) {
            uint32_t a[4][4], bb[2][4];
#pragma unroll
            for (int mt = 0; mt < 4; mt++) ldsm4(a[mt],  st + aRow[mt] + csw[ks]);
#pragma unroll
            for (int np = 0; np < 2; np++) ldsm4(bb[np], st + bRow[np] + csw[ks]);
#pragma unroll
            for (int mt = 0; mt < 4; mt++)
#pragma unroll
                for (int nt = 0; nt < 4; nt++)
                    mma_f16(acc[mt][nt], a[mt], bb[nt >> 1][nt & 1], bb[nt >> 1][2 + (nt & 1)]);
        }
    }

    // ---- epilogue ----
    const float invs = inv_in ? __ldg(inv_in) : 1.0f;
    const float osc  = sc_out ? __ldg(sc_out) : 1.0f;
    float lmin = 3.4e38f;
    const int gid = lane >> 2, tig = lane & 3;
    float*  Cf = (float*)Cv;
    __half* Ch = (__half*)Cv;
#pragma unroll
    for (int mt = 0; mt < 4; mt++) {
        const int row = blockIdx.y * 128 + wm * 64 + mt * 16 + gid;
        float nr0 = 0.0f, nr8 = 0.0f;
        if (EPI == EPI_D2) { nr0 = __ldg(e1 + row); nr8 = __ldg(e1 + row + 8); }
        float ns0 = 0.0f, ns8 = 0.0f;
#pragma unroll
        for (int nt = 0; nt < 4; nt++) {
            const int col = blockIdx.x * 128 + wn * 32 + nt * 8 + tig * 2;
            float ec0 = 0.0f, ec1 = 0.0f;
            if (EPI == EPI_BIAS || EPI == EPI_BIAS_MISH || EPI == EPI_D2) {
                const float* ee = (EPI == EPI_D2) ? e2 : e1;
                ec0 = __ldg(ee + col); ec1 = __ldg(ee + col + 1);
            }
            float v[4] = {acc[mt][nt][0], acc[mt][nt][1], acc[mt][nt][2], acc[mt][nt][3]};
#pragma unroll
            for (int q = 0; q < 4; q++) {
                float x = v[q] * invs;
                const float ec = (q & 1) ? ec1 : ec0;
                const float nr = (q < 2) ? nr0 : nr8;
                if (EPI == EPI_BIAS)           x = x + ec;
                else if (EPI == EPI_BIAS_MISH) x = mish_f(x + ec);
                else if (EPI == EPI_MISH)      x = mish_f(x);
                else if (EPI == EPI_D2) {      // raw clamped d2 — NO MUFU here
                    x = fmaxf(nr + ec - 2.0f * x, 0.0f);
                    if (TRACK_MIN) lmin = fminf(lmin, x);
                }
                v[q] = x * osc;
            }
            if (HALF_OUT) {
                __half2 ha = __floats2half2_rn(v[0], v[1]);
                __half2 hb = __floats2half2_rn(v[2], v[3]);
                *(__half2*)(Ch + (size_t)row * N + col)       = ha;
                *(__half2*)(Ch + (size_t)(row + 8) * N + col) = hb;
                if (NORM_OUT) {
                    float2 fa = __half22float2(ha), fb = __half22float2(hb);
                    ns0 += fa.x * fa.x + fa.y * fa.y;
                    ns8 += fb.x * fb.x + fb.y * fb.y;
                }
            } else {
                // NORMAL store policy: keep the d2 master hot in L2 for the
                // convert pass that launches immediately after.
                *(float2*)(Cf + (size_t)row * N + col)       = make_float2(v[0], v[1]);
                *(float2*)(Cf + (size_t)(row + 8) * N + col) = make_float2(v[2], v[3]);
            }
        }
        if (NORM_OUT) {
            ns0 += __shfl_down_sync(0xffffffffu, ns0, 2);
            ns0 += __shfl_down_sync(0xffffffffu, ns0, 1);
            ns8 += __shfl_down_sync(0xffffffffu, ns8, 2);
            ns8 += __shfl_down_sync(0xffffffffu, ns8, 1);
            if (tig == 0) {
                atomicAdd(nrm_out + row,     ns0);
                atomicAdd(nrm_out + row + 8, ns8);
            }
        }
    }
    if (TRACK_MIN) {
#pragma unroll
        for (int o = 16; o; o >>= 1) lmin = fminf(lmin, __shfl_xor_sync(0xffffffffu, lmin, o));
        if (lane == 0) atomicMin(&g_minD2, __float_as_uint(lmin));  // d2 >= 0: uint order ok
        __syncthreads();
        // last CTA derives the scales (no separate kernel)
        if (tid == 0) {
            __threadfence();
            unsigned n = gridDim.x * gridDim.y;
            if (atomicAdd(&g_done, 1u) == n - 1u) {
                float dmin = sqrtf(__uint_as_float(*(volatile unsigned*)&g_minD2));
                // E ~= ilogb(maxK), maxK = exp(-dmin); +/-1 slack keeps
                // maxK*scK within [2^12, 2^15] — far below fp16 max.
                int E = (int)floorf(-dmin * 1.44269504f);
                g_sc[0] = (float)(13 - E);            // exponent addend for exp2
                g_sc[1] = exp2f((float)(E - 13));     // invK
                g_sc[2] = exp2f((float)(7 - E));      // scH  (|h| < 64*maxK)
                g_sc[3] = exp2f((float)(E - 7));      // invH
                g_done = 0;                           // reset for next replay
                __threadfence();
            }
        }
    }
}

// ---------------------------------------------------------------------------
// Fused input conversion (grid-stride): all six fp32 inputs -> fp16;
// zero nrm; init g_minD2 = +inf.
// ---------------------------------------------------------------------------
__device__ __forceinline__ void cvt_gs(const float4* in, uint2* out, int n4) {
    for (int i = blockIdx.x * 256 + threadIdx.x; i < n4; i += gridDim.x * 256) {
        float4 v = in[i];
        __half2 a = __floats2half2_rn(v.x, v.y);
        __half2 b = __floats2half2_rn(v.z, v.w);
        uint2 o;
        o.x = *(const unsigned*)&a;
        o.y = *(const unsigned*)&b;
        out[i] = o;
    }
}

__global__ void __launch_bounds__(256)
f2h_all(const float4* x, const float4* sm, const float4* w1, const float4* w2,
        const float4* wn1, const float4* wn2,
        uint2* cath, uint2* w1h, uint2* w2h, uint2* wn1h, uint2* wn2h,
        float4* nrm)
{
    switch (blockIdx.y) {
        case 0: cvt_gs(x,   cath,               NB * ND / 4); break;
        case 1: cvt_gs(sm,  cath + NB * ND / 4, NS * ND / 4); break;
        case 2: cvt_gs(w1,  w1h,                ND * ND / 4);
                for (int j = blockIdx.x * 256 + threadIdx.x; j < NM / 4; j += gridDim.x * 256)
                    nrm[j] = make_float4(0.f, 0.f, 0.f, 0.f);
                if (blockIdx.x == 0 && threadIdx.x == 0) g_minD2 = 0x7F800000u; // +inf
                break;
        case 3: cvt_gs(w2,  w2h,                ND * ND / 4); break;
        case 4: cvt_gs(wn1, wn1h,               NS * NS / 4); break;
        case 5: cvt_gs(wn2, wn2h,               NS * NS / 4); break;
    }
}

// ---------------------------------------------------------------------------
// d2 master -> scaled fp16 K: K*2^s = exp2(s - sqrt(d2)*log2e).
// Loads evict-after-read (frees L2 for Kh, which mish re-reads 16x);
// MUFU work hides under memory latency.
// ---------------------------------------------------------------------------
__device__ __forceinline__ float d2K(float d2, float s13) {
    float d;
    asm("sqrt.approx.f32 %0, %1;" : "=f"(d) : "f"(d2));
    return exp2f(fmaf(-d, 1.44269504f, s13));
}

__global__ void __launch_bounds__(256)
d2_to_Kh(const float4* __restrict__ in, uint2* __restrict__ out, int n4,
         const float* __restrict__ sc)
{
    const float s13 = __ldg(sc);
    const int stride = gridDim.x * 256;
    for (int i0 = blockIdx.x * 256 + threadIdx.x; i0 < n4; i0 += stride * 4) {
#pragma unroll
        for (int t = 0; t < 4; t++) {
            int i = i0 + t * stride;
            if (i < n4) {
                float4 v = __ldcs(in + i);
                __half2 a = __floats2half2_rn(d2K(v.x, s13), d2K(v.y, s13));
                __half2 b = __floats2half2_rn(d2K(v.z, s13), d2K(v.w, s13));
                uint2 o;
                o.x = *(const unsigned*)&a;
                o.y = *(const unsigned*)&b;
                out[i] = o;
            }
        }
    }
}

// ---------------------------------------------------------------------------
// Launch — 7 launches; our index 3 = d2 GEMM (grid 2048) = ncu capture slot.
// ---------------------------------------------------------------------------
extern "C" void kernel_launch(void* const* d_in, const int* in_sizes, int n_in,
                              void* d_out, int out_size)
{
    const float* x   = (const float*)d_in[0];
    const float* sm  = (const float*)d_in[1];
    const float* W1  = (const float*)d_in[2];
    const float* b1  = (const float*)d_in[3];
    const float* W2  = (const float*)d_in[4];
    const float* b2  = (const float*)d_in[5];
    const float* Wn1 = (const float*)d_in[6];
    const float* Wn2 = (const float*)d_in[7];
    float* out = (float*)d_out;

    __half *cath, *t1h, *dmlh, *W1h, *W2h, *Wn1h, *Wn2h, *Kh, *Hh;
    float *Kf, *nrm, *sc;
    cudaGetSymbolAddress((void**)&cath, g_cath);
    cudaGetSymbolAddress((void**)&t1h,  g_t1h);
    cudaGetSymbolAddress((void**)&dmlh, g_dmlh);
    cudaGetSymbolAddress((void**)&W1h,  g_W1h);
    cudaGetSymbolAddress((void**)&W2h,  g_W2h);
    cudaGetSymbolAddress((void**)&Wn1h, g_Wn1h);
    cudaGetSymbolAddress((void**)&Wn2h, g_Wn2h);
    cudaGetSymbolAddress((void**)&Kf,   g_Kf);
    cudaGetSymbolAddress((void**)&Kh,   g_Kh);
    cudaGetSymbolAddress((void**)&Hh,   g_Hh);
    cudaGetSymbolAddress((void**)&nrm,  g_nrm);
    cudaGetSymbolAddress((void**)&sc,   g_sc);

    #define SETSM(KER) cudaFuncSetAttribute(KER, cudaFuncAttributeMaxDynamicSharedMemorySize, DSMEM_BY)
    SETSM((gemm_h<EPI_BIAS_MISH, true,  false, false>));
    SETSM((gemm_h<EPI_BIAS,      true,  false, true >));
    SETSM((gemm_h<EPI_D2,        false, true,  false>));
    SETSM((gemm_h<EPI_MISH,      true,  false, false>));
    SETSM((gemm_h<EPI_NONE,      false, false, false>));
    #undef SETSM

    const dim3 blk(256);
    const dim3 gDml(ND / 128, NM / 128);
    const dim3 gBig(NS / 128, NB / 128);

    // idx 0: fused conversion of ALL inputs + zero nrm / init minD2
    f2h_all<<<dim3(1024, 6), 256>>>(
        (const float4*)x, (const float4*)sm, (const float4*)W1, (const float4*)W2,
        (const float4*)Wn1, (const float4*)Wn2,
        (uint2*)cath, (uint2*)W1h, (uint2*)W2h, (uint2*)Wn1h, (uint2*)Wn2h,
        (float4*)nrm);

    // idx 1: dml layer 1 (fused x+samples)
    gemm_h<EPI_BIAS_MISH, true, false, false><<<gDml, blk, DSMEM_BY>>>(
        cath, W1h, t1h, NM, ND, ND, b1, nullptr, nullptr, nullptr, nullptr);

    // idx 2: dml layer 2 + fused row norms (of stored fp16 values)
    gemm_h<EPI_BIAS, true, false, true><<<gDml, blk, DSMEM_BY>>>(
        t1h, W2h, dmlh, NM, ND, ND, b2, nullptr, nullptr, nullptr, nrm);

    // idx 3: d2 GEMM — ncu capture target; MUFU-free epilogue; L2-resident
    // master; last CTA derives the K/H scales from min d2
    gemm_h<EPI_D2, false, true, false><<<gBig, blk, DSMEM_BY>>>(
        dmlh, dmlh + (size_t)NB * ND, Kf, NB, NS, ND, nrm, nrm + NB,
        nullptr, nullptr, nullptr);

    // idx 4: d2 -> scaled fp16 K (reads mostly L2-hot master)
    d2_to_Kh<<<2048, 256>>>(
        (const float4*)Kf, (uint2*)Kh, (int)((long long)NB * NS / 4), sc);

    // idx 5: h' = mish((K' @ Wn1^T)*invK) * scH -> fp16 direct
    gemm_h<EPI_MISH, true, false, false><<<gBig, blk, DSMEM_BY>>>(
        Kh, Wn1h, Hh, NB, NS, NS, nullptr, nullptr, sc + 1, sc + 2, nullptr);

    // idx 6: out = (h' @ Wn2^T) * invH  (fp32)
    gemm_h<EPI_NONE, false, false, false><<<gBig, blk, DSMEM_BY>>>(
        Hh, Wn2h, out, NB, NS, NS, nullptr, nullptr, sc + 3, nullptr, nullptr);
}